// round 15
// baseline (speedup 1.0000x reference)
#include <cuda_runtime.h>
#include <cuda_bf16.h>
#include <cstdint>

#define MAXN 32768
#define MAXE 32768
#define MEM  150
#define JPAD 512
#define NCLUST 36

// ---- shared-memory byte offsets (same layout in every CTA) ----
#define OFF_GMB     0               // 2 gate mbarriers (8B each)
#define OFF_TMB     16              // 2 ticket mbarriers
#define OFF_TICKBUF 32              // 2 ints (double-buffered ticket)
#define OFF_SA      40              // 2 floats (double-buffered attention scalar)
#define OFF_GATE    64              // 2 slots * 480 floats -> [64, 3904)
#define OFF_VSM     3904            // 304 floats (h 0..151 | k 152..303), 16B aligned
#define OFF_W       5120            // h-half weights: 38*160 float4 = 97280B
#define EDGE_SMEM   (OFF_W + 38*160*16)
#define GATE_TX     1804            // 3*150*4 gate bytes + 4 bytes attention scalar

// ---------------- static device scratch (no allocations allowed) ------------
__device__ float g_state[MAXN * MEM];            // node K (published for chain tops + leaves)
__device__ float g_stat [MAXN * JPAD];           // per-node static: Ww@w + Wt@tag + bias
__device__ float g_rel  [MAXN * JPAD];           // per-node: Wrel@rel
__device__ float g_leafpre[MAXN * JPAD];         // leaf GRU pre-activations
__device__ float g_kpre [MAXN * JPAD];           // leaf nodes: Wk@K[leaf] precomputed
__device__ float g_WcombT[320 * JPAD];           // [w|tag] static weights, i-major
__device__ float g_leafWT [320 * JPAD];          // leaf_W transposed, i-major
__device__ float g_WkT   [160 * JPAD];           // k-part weights, i-major (for kpre GEMM)
__device__ float g_WrelT  [20  * JPAD];
__device__ float4 g_dyn4[76 * JPAD];             // dyn weights: vi 0..149=U(h), 152..301=Wk(k)
__device__ float g_bias[JPAD];
__device__ float g_c0[JPAD];                     // leaf: leaf_U@leaf_h + leaf_b
__device__ int   g_child_ready[MAXN];            // 0=not ready, 1=done
__device__ int   g_run_start[MAXE + 1];
__device__ int   g_run_of[MAXN];                 // node -> run id (-1 = leaf)
__device__ int   g_desig[MAXN];                  // node -> max-height child (chain link)
__device__ int   g_parent_of[MAXN];              // child -> parent
__device__ int   g_echild[MAXE];                 // child | (leaf << 31)
__device__ int   g_path_top[MAXE];               // chain tops, node index descending
__device__ int   g_height[MAXN];                 // subtree height (leaf = 0)
__device__ int   g_internal[MAXN];               // internal node list (unordered)
__device__ int   g_NI;
__device__ int   g_P;                            // number of chains
__device__ int   g_R;
__device__ int   g_ticket;

// ---------------- asm helpers ----------------
__device__ __forceinline__ int ld_acq(const int* p) {
    int v;
    asm volatile("ld.acquire.gpu.global.b32 %0, [%1];" : "=r"(v) : "l"(p) : "memory");
    return v;
}
__device__ __forceinline__ void st_rel(int* p, int v) {
    asm volatile("st.release.gpu.global.b32 [%0], %1;" :: "l"(p), "r"(v) : "memory");
}
__device__ __forceinline__ float sigf(float x) { return 1.f / (1.f + expf(-x)); }
__device__ __forceinline__ uint32_t smem_u32(const void* p) {
    return (uint32_t)__cvta_generic_to_shared(p);
}
__device__ __forceinline__ uint32_t cluster_rank() {
    uint32_t r; asm("mov.u32 %0, %%cluster_ctarank;" : "=r"(r)); return r;
}
__device__ __forceinline__ uint32_t mapa_rank(uint32_t addr, uint32_t rank) {
    uint32_t r;
    asm("mapa.shared::cluster.u32 %0, %1, %2;" : "=r"(r) : "r"(addr), "r"(rank));
    return r;
}
__device__ __forceinline__ void mbar_init(uint32_t a, uint32_t cnt) {
    asm volatile("mbarrier.init.shared.b64 [%0], %1;" :: "r"(a), "r"(cnt) : "memory");
}
__device__ __forceinline__ void mbar_expect_tx(uint32_t a, uint32_t bytes) {
    asm volatile("mbarrier.arrive.expect_tx.shared.b64 _, [%0], %1;" :: "r"(a), "r"(bytes) : "memory");
}
__device__ __forceinline__ void st_async_b32(uint32_t remAddr, uint32_t v, uint32_t remMbar) {
    asm volatile("st.async.shared::cluster.mbarrier::complete_tx::bytes.b32 [%0], %1, [%2];"
                 :: "r"(remAddr), "r"(v), "r"(remMbar) : "memory");
}
__device__ __forceinline__ void mbar_wait(uint32_t a, uint32_t parity) {
    uint32_t done;
    do {
        asm volatile(
            "{\n\t.reg .pred p;\n\t"
            "mbarrier.try_wait.parity.acquire.cluster.shared::cta.b64 p, [%1], %2, 0x989680;\n\t"
            "selp.b32 %0, 1, 0, p;\n\t}"
            : "=r"(done) : "r"(a), "r"(parity) : "memory");
    } while (!done);
}
__device__ __forceinline__ void cluster_sync2() {
    asm volatile("barrier.cluster.arrive.aligned;" ::: "memory");
    asm volatile("barrier.cluster.wait.aligned;" ::: "memory");
}

// column -> (gru row | att row) mapping
__device__ __forceinline__ void colmap(int j, int& row, int& q) {
    row = -1; q = -1;
    if (j < 480) { int m = j % 160; if (m < 150) row = (j / 160) * 150 + m; }
    else if (j < 500) q = j - 480;
}

// ---------------- init ----------------
__global__ void k_init(int N, int E) {
    int stride = gridDim.x * blockDim.x;
    int t0 = blockIdx.x * blockDim.x + threadIdx.x;
    for (int i = t0; i < N; i += stride) { g_child_ready[i] = 0; g_run_of[i] = -1; }
    if (t0 == 0) { g_ticket = 0; g_NI = 0; }
}

// ---------------- run table (single block scan) ----------------
__global__ void k_runscan(const int* __restrict__ ed, int E) {
    __shared__ int sflag[1024];
    __shared__ int sbase;
    int tid = threadIdx.x;
    if (tid == 0) sbase = 0;
    __syncthreads();
    for (int chunk = 0; chunk < E; chunk += 1024) {
        int i = chunk + tid;
        int f = 0;
        if (i < E) f = (i == 0) || (ed[2 * i] != ed[2 * i - 2]);
        sflag[tid] = f;
        __syncthreads();
        for (int off = 1; off < 1024; off <<= 1) {
            int v = (tid >= off) ? sflag[tid - off] : 0;
            __syncthreads();
            sflag[tid] += v;
            __syncthreads();
        }
        if (i < E && f) {
            int rid = sbase + sflag[tid] - 1;
            int p = ed[2 * i];
            g_run_start[rid] = i;
            g_run_of[p] = rid;
        }
        __syncthreads();
        if (tid == 0) sbase += sflag[1023];
        __syncthreads();
    }
    if (tid == 0) { g_R = sbase; g_run_start[sbase] = E; }
}

// ---------------- parent map + packed child array + internal list -----------
__global__ void k_parent(const int* __restrict__ ed, int E) {
    int i = blockIdx.x * blockDim.x + threadIdx.x;
    if (i < E) {
        int c = ed[2 * i + 1];
        g_parent_of[c] = ed[2 * i];
        g_echild[i] = c | ((g_run_of[c] < 0) ? (int)0x80000000 : 0);
    }
    if (i == 0) g_parent_of[0] = -1;
}
__global__ void k_intlist(int N) {
    int n = blockIdx.x * blockDim.x + threadIdx.x;
    if (n < N && g_run_of[n] >= 0) g_internal[atomicAdd(&g_NI, 1)] = n;
}

// ---------------- subtree heights (one block, descending 1024-chunks) -------
// child index > parent, child <= parent+64 -> deps are upward in index.
__global__ void k_height(int N) {
    __shared__ int sh[1024];
    __shared__ unsigned char sdone[1024];
    __shared__ int sleft;
    int tid = threadIdx.x;
    for (int base = ((N - 1) / 1024) * 1024; base >= 0; base -= 1024) {
        int n = base + tid;
        bool active = (n < N);
        int rid = active ? g_run_of[n] : -1;
        int es = 0, ee = 0;
        if (rid >= 0) { es = g_run_start[rid]; ee = g_run_start[rid + 1]; }
        bool done = (!active) || (rid < 0);        // leaves resolve to 0
        sh[tid] = 0;
        sdone[tid] = done ? 1 : 0;
        __syncthreads();
        while (true) {
            if (tid == 0) sleft = 0;
            __syncthreads();
            if (!done) {
                bool ok = true; int hm = 0;
                for (int e = es; e < ee; e++) {
                    int c = g_echild[e] & 0x7fffffff;
                    int hc;
                    if (c >= base && c < base + 1024) {
                        if (!sdone[c - base]) { ok = false; break; }
                        hc = sh[c - base];
                    } else {
                        hc = g_height[c];          // higher chunk, already final
                    }
                    if (hc > hm) hm = hc;
                }
                if (ok) {
                    sh[tid] = hm + 1;
                    __threadfence_block();
                    sdone[tid] = 1;
                    done = true;
                }
            }
            if (!done) atomicAdd(&sleft, 1);
            __syncthreads();
            if (sleft == 0) break;
            __syncthreads();
        }
        if (active) g_height[n] = sh[tid];
        __syncthreads();
    }
}

// ---------------- designated child = argmax subtree height ----------------
__global__ void k_desig2(int N) {
    int n = blockIdx.x * blockDim.x + threadIdx.x;
    if (n >= N) return;
    int rid = g_run_of[n];
    if (rid < 0) return;
    int es = g_run_start[rid], ee = g_run_start[rid + 1];
    int best = -1, bh = -1;
    for (int e = es; e < ee; e++) {
        int c = g_echild[e] & 0x7fffffff;
        int hc = g_height[c];
        if (hc > bh) { bh = hc; best = c; }
    }
    g_desig[n] = best;
}

// ---------------- chain tops, node index descending (single block scan) -----
__global__ void k_pathscan(int N) {
    __shared__ int sflag[1024];
    __shared__ int sbase;
    int tid = threadIdx.x;
    if (tid == 0) sbase = 0;
    __syncthreads();
    for (int chunk = 0; chunk < N; chunk += 1024) {
        int nr = chunk + tid;
        int n = N - 1 - nr;
        int f = 0;
        if (nr < N && g_run_of[n] >= 0) {          // internal node
            if (n == 0) f = 1;
            else f = (g_desig[g_parent_of[n]] != n) ? 1 : 0;   // not chain-linked
        }
        sflag[tid] = f;
        __syncthreads();
        for (int off = 1; off < 1024; off <<= 1) {
            int v = (tid >= off) ? sflag[tid - off] : 0;
            __syncthreads();
            sflag[tid] += v;
            __syncthreads();
        }
        if (f) g_path_top[sbase + sflag[tid] - 1] = n;
        __syncthreads();
        if (tid == 0) sbase += sflag[1023];
        __syncthreads();
    }
    if (tid == 0) g_P = sbase;
}

// ---------------- weight reshuffles ----------------
// node_W: (450,490), x layout: [word 0..299 | K 300..449 | rel 450..469 | tag 470..489]
__global__ void k_build_big(const float* __restrict__ node_W, const float* __restrict__ node_U,
                            const float* __restrict__ at_Wb,  const float* __restrict__ leaf_W) {
    int idx = blockIdx.x * blockDim.x + threadIdx.x;
    if (idx >= 320 * JPAD) return;
    int i = idx / JPAD, j = idx % JPAD;
    int row, q; colmap(j, row, q);
    float v = 0.f;
    if (row >= 0)      v = (i < 300) ? node_W[row * 490 + i] : node_W[row * 490 + 470 + (i - 300)];
    else if (q >= 0)   v = (i < 300) ? at_Wb[q * 490 + i]    : at_Wb[q * 490 + 470 + (i - 300)];
    g_WcombT[idx] = v;
    g_leafWT[idx] = (row >= 0) ? leaf_W[row * 320 + i] : 0.f;
    if (i < 304) {
        float mv = 0.f;
        if (i < 150) {
            if (row >= 0) mv = node_U[row * 150 + i];
        } else if (i >= 152 && i < 302) {
            int kk = i - 152;
            if (row >= 0)      mv = node_W[row * 490 + 300 + kk];
            else if (q >= 0)   mv = at_Wb[q * 490 + 300 + kk];
        }
        reinterpret_cast<float*>(g_dyn4)[((i >> 2) * JPAD + j) * 4 + (i & 3)] = mv;
    }
    if (i < 160) {
        float kv = 0.f;
        if (i < 150) {
            if (row >= 0)      kv = node_W[row * 490 + 300 + i];
            else if (q >= 0)   kv = at_Wb[q * 490 + 300 + i];
        }
        g_WkT[i * JPAD + j] = kv;
    }
}

__global__ void k_build_small(const float* __restrict__ node_W, const float* __restrict__ at_Wb,
                              const float* __restrict__ node_b, const float* __restrict__ at_bb) {
    int idx = blockIdx.x * blockDim.x + threadIdx.x;
    if (idx < 20 * JPAD) {
        int i = idx / JPAD, j = idx % JPAD;
        int row, q; colmap(j, row, q);
        float v = 0.f;
        if (row >= 0)    v = node_W[row * 490 + 450 + i];
        else if (q >= 0) v = at_Wb[q * 490 + 450 + i];
        g_WrelT[idx] = v;
    } else if (idx < 21 * JPAD) {
        int j = idx - 20 * JPAD;
        int row, q; colmap(j, row, q);
        if (row >= 0)      g_bias[j] = node_b[row];
        else if (q >= 0)   g_bias[j] = at_bb[q];
        else               g_bias[j] = 0.f;
    }
}

__global__ void k_c0(const float* __restrict__ leaf_U, const float* __restrict__ leaf_h,
                     const float* __restrict__ leaf_b) {
    int j = threadIdx.x;
    if (j >= JPAD) return;
    int row, q; colmap(j, row, q);
    float v = 0.f;
    if (row >= 0) {
        v = leaf_b[row];
        for (int n = 0; n < MEM; n++) v += leaf_U[row * 150 + n] * leaf_h[n];
    }
    g_c0[j] = v;
}

// ---------------- tiled GEMM ----------------
// mode 0: g_stat[g_internal[r]][j] = [w|tag] @ WcombT + bias (M=g_NI, K=320)
// mode 1: g_leafpre[l][j] = [w|tag][lids[l]] @ leafWT + c0   (M=L, K=320)
// mode 2: g_kpre[lids[l]][j] = K_leaf[l] @ WkT               (M=L, K=160)
#define BM 64
#define BN 64
#define BK 16
__global__ void __launch_bounds__(256) k_gemm(int mode, int M, int Ktot,
                                              const float* __restrict__ w_emb,
                                              const float* __restrict__ tag_emb,
                                              const int* __restrict__ lids) {
    __shared__ float As[BK][BM + 4];
    __shared__ float Bs[BK][BN];
    const float* B = (mode == 0) ? g_WcombT : ((mode == 1) ? g_leafWT : g_WkT);
    const int* rmap = (mode == 0) ? g_internal : lids;
    int MM = (mode == 0) ? g_NI : M;
    int tid = threadIdx.x;
    int tx = tid & 15, ty = tid >> 4;
    int m0 = blockIdx.x * BM, j0 = blockIdx.y * BN;
    if (m0 >= MM) return;
    int ka = tid & 15, ma = tid >> 4;
    int jb = tid & 63, kb = tid >> 6;
    float acc[4][4] = {};
    for (int k0 = 0; k0 < Ktot; k0 += BK) {
        #pragma unroll
        for (int it = 0; it < 4; it++) {
            int r = m0 + ma + 16 * it;
            if (r >= MM) r = MM - 1;
            int row = rmap[r];
            int i = k0 + ka;
            float av;
            if (mode == 2) av = (i < 150) ? g_state[row * MEM + i] : 0.f;
            else av = (i < 300) ? w_emb[row * 300 + i] : tag_emb[row * 20 + (i - 300)];
            As[ka][ma + 16 * it] = av;
        }
        #pragma unroll
        for (int it = 0; it < 4; it++)
            Bs[kb + 4 * it][jb] = B[(k0 + kb + 4 * it) * JPAD + (j0 + jb)];
        __syncthreads();
        #pragma unroll
        for (int k = 0; k < BK; k++) {
            float4 a4 = *(const float4*)&As[k][ty * 4];
            float4 b4 = *(const float4*)&Bs[k][tx * 4];
            float av[4] = {a4.x, a4.y, a4.z, a4.w};
            float bv[4] = {b4.x, b4.y, b4.z, b4.w};
            #pragma unroll
            for (int mm = 0; mm < 4; mm++)
                #pragma unroll
                for (int jj = 0; jj < 4; jj++)
                    acc[mm][jj] = fmaf(av[mm], bv[jj], acc[mm][jj]);
        }
        __syncthreads();
    }
    #pragma unroll
    for (int mm = 0; mm < 4; mm++) {
        int r = m0 + ty * 4 + mm;
        if (r >= MM) continue;
        #pragma unroll
        for (int jj = 0; jj < 4; jj++) {
            int j = j0 + tx * 4 + jj;
            int row = rmap[r];
            if (mode == 0)      g_stat[(size_t)row * JPAD + j] = acc[mm][jj] + g_bias[j];
            else if (mode == 1) g_leafpre[(size_t)r * JPAD + j] = acc[mm][jj] + g_c0[j];
            else                g_kpre[(size_t)row * JPAD + j] = acc[mm][jj];
        }
    }
}

// ---------------- rel projection (K=20) ----------------
__global__ void __launch_bounds__(512) k_relpart(const float* __restrict__ rel_emb) {
    int n = blockIdx.x, j = threadIdx.x;
    float acc = 0.f;
    #pragma unroll
    for (int q = 0; q < 20; q++)
        acc = fmaf(g_WrelT[q * JPAD + j], __ldg(&rel_emb[n * 20 + q]), acc);
    g_rel[n * JPAD + j] = acc;
}

// ---------------- leaf epilogue ----------------
__global__ void k_leafcomb(const int* __restrict__ lids, const float* __restrict__ leaf_h, int L) {
    int idx = blockIdx.x * blockDim.x + threadIdx.x;
    if (idx >= L * MEM) return;
    int l = idx / MEM, m = idx % MEM;
    float z  = sigf (g_leafpre[l * JPAD + m]);
    float r  = sigf (g_leafpre[l * JPAD + 160 + m]);
    float ht = tanhf(g_leafpre[l * JPAD + 320 + m]);
    g_state[lids[l] * MEM + m] = r * leaf_h[m] + (1.f - z) * ht;
}

// ---------------- persistent cluster-4 chain kernel -------------------------
// Chains follow the MAX-HEIGHT child: the (statically likely) critical
// dependency stays inside the cluster, stashed in kcache registers.
// roles 0/1/2: z/r/ht gate CTAs (160 cols); role 3: attention (32 cols)
// warp 5 (tid 160) = dedicated dependency poller, overlaps h-matvec.
__global__ void __launch_bounds__(192, 1) __cluster_dims__(4, 1, 1)
k_edges(const float* __restrict__ at_Wa, const float* __restrict__ at_ba) {
    extern __shared__ char smem[];
    volatile int*   tickbuf = (volatile int*)(smem + OFF_TICKBUF);
    volatile float* sa_sh   = (volatile float*)(smem + OFF_SA);
    float*  gatebuf = (float*)(smem + OFF_GATE);   // [2][480]
    float*  vsm  = (float*)(smem + OFF_VSM);
    float4* vsm4 = (float4*)vsm;
    float4* sw4  = (float4*)(smem + OFF_W);        // h-half weights only (rows 0..37)
    uint32_t base = smem_u32(smem);

    int tid = threadIdx.x;
    int role = (int)cluster_rank();
    bool comp = (tid < 160);

    // k-half weights in registers
    float4 wk[38];
    if (role < 3) {
        if (comp) {
            int j0 = role * 160;
            #pragma unroll
            for (int r = 0; r < 38; r++) {
                sw4[r * 160 + tid] = g_dyn4[r * JPAD + j0 + tid];          // h rows
                wk[r] = g_dyn4[(38 + r) * JPAD + j0 + tid];                // k rows
            }
        }
    } else if (tid < 32) {
        #pragma unroll
        for (int r = 0; r < 38; r++)
            wk[r] = g_dyn4[(38 + r) * JPAD + 480 + tid];
    }
    if (tid < 4) vsm[150 + (tid >> 1) * 152 + (tid & 1)] = 0.f;  // pads 150,151,302,303
    __syncthreads();

    if (tid == 0) {
        mbar_init(base + OFF_GMB, 1);      mbar_init(base + OFF_GMB + 8, 1);
        mbar_init(base + OFF_TMB, 1);      mbar_init(base + OFF_TMB + 8, 1);
    }
    __syncthreads();
    if (tid == 0) {
        mbar_expect_tx(base + OFF_GMB,     GATE_TX);
        mbar_expect_tx(base + OFF_GMB + 8, GATE_TX);
        mbar_expect_tx(base + OFF_TMB,     4);
        mbar_expect_tx(base + OFF_TMB + 8, 4);
    }
    __syncthreads();

    uint32_t rb0 = mapa_rank(base, 0), rb1 = mapa_rank(base, 1);
    uint32_t rb2 = mapa_rank(base, 2), rb3 = mapa_rank(base, 3);

    float ba = 0.f, wa = 0.f;
    if (role == 3) { ba = *at_ba; wa = (tid < 20) ? at_Wa[tid] : 0.f; }

    cluster_sync2();                               // all barriers armed cluster-wide

    if (role == 0 && tid == 0) {                   // bootstrap ticket -> slot 0
        int e0 = atomicAdd(&g_ticket, 1);
        st_async_b32(rb0 + OFF_TICKBUF, (uint32_t)e0, rb0 + OFF_TMB);
        st_async_b32(rb1 + OFF_TICKBUF, (uint32_t)e0, rb1 + OFF_TMB);
        st_async_b32(rb2 + OFF_TICKBUF, (uint32_t)e0, rb2 + OFF_TMB);
        st_async_b32(rb3 + OFF_TICKBUF, (uint32_t)e0, rb3 + OFF_TMB);
    }

    int P = g_P;
    int epar = 0;
    uint32_t gph0 = 0, gph1 = 0;
    int tslot = 0; uint32_t tph0 = 0, tph1 = 0;

    while (true) {
        // ---- ticket rendezvous ----
        uint32_t tmbL = base + OFF_TMB + 8u * (uint32_t)tslot;
        mbar_wait(tmbL, tslot ? tph1 : tph0);
        if (tslot) tph1 ^= 1; else tph0 ^= 1;
        int r = tickbuf[tslot];
        __syncthreads();                           // all read before re-arm
        if (tid == 0) mbar_expect_tx(tmbL, 4);
        if (r >= P) break;
        bool sendNext = (role == 0 && tid == 0);
        tslot ^= 1;

        int t = __ldg(&g_path_top[r]);
        int v = t;
        while (true) {
            int d = __ldg(&g_desig[v]);
            if (__ldg(&g_run_of[d]) < 0) break;
            v = d;
        }
        int cache_id = -1;
        float kcache = 0.f;                        // K[cache_id] element (tid<150)

        while (true) {                             // chain bottom-up
            int rid = __ldg(&g_run_of[v]);
            int es = __ldg(&g_run_start[rid]), ee = __ldg(&g_run_start[rid + 1]);

            float statv = 0.f;
            if (role < 3) { if (comp) statv = __ldg(&g_stat[(size_t)v * JPAD + role * 160 + tid]); }
            else if (tid < 32) statv = __ldg(&g_stat[(size_t)v * JPAD + 480 + tid]);

            // prefetch first edge of run
            int ce = __ldg(&g_echild[es]);
            int c = ce & 0x7fffffff;
            bool cleaf = (ce < 0);
            float relv = 0.f, kprev = 0.f;
            if (role < 3) { if (comp) relv = __ldg(&g_rel[(size_t)c * JPAD + role * 160 + tid]); }
            else if (tid < 32) relv = __ldg(&g_rel[(size_t)c * JPAD + 480 + tid]);
            if (cleaf) {
                if (role < 3) { if (comp) kprev = __ldg(&g_kpre[(size_t)c * JPAD + role * 160 + tid]); }
                else if (tid < 32) kprev = __ldg(&g_kpre[(size_t)c * JPAD + 480 + tid]);
            }

            bool first = true;
            float hreg = 0.f;

            for (int e = es; e < ee; e++) {
                bool cached = (c == cache_id);
                float mx = 0.f, my = 0.f, mz = 0.f, mw = 0.f;   // 4 split accumulators

                // dedicated poller (warp 5) overlaps the h-matvec below
                if (tid == 160 && !cleaf && !cached) {
                    int n = 0;
                    while (!ld_acq(&g_child_ready[c])) { if (++n > 256) __nanosleep(32); }
                }
                if (!first && role < 3 && comp) {
                    const float4* wp = sw4 + tid;
                    #pragma unroll 4
                    for (int r2 = 0; r2 < 38; r2++) {
                        float4 w = wp[r2 * 160]; float4 v4 = vsm4[r2];
                        mx = fmaf(w.x, v4.x, mx); my = fmaf(w.y, v4.y, my);
                        mz = fmaf(w.z, v4.z, mz); mw = fmaf(w.w, v4.w, mw);
                    }
                }
                __syncthreads();                   // join poll + h-matvec

                if (!cleaf) {
                    if (cached) {                  // chain-local child: from registers
                        if (tid < 150) vsm[152 + tid] = kcache;
                    } else {
                        if (tid < 150) vsm[152 + tid] = __ldcg(&g_state[c * MEM + tid]);
                    }
                    __syncthreads();
                    if ((role < 3 && comp) || (role == 3 && tid < 32)) {
                        #pragma unroll 4
                        for (int r2 = 0; r2 < 38; r2++) {
                            float4 w = wk[r2]; float4 v4 = vsm4[38 + r2];
                            mx = fmaf(w.x, v4.x, mx); my = fmaf(w.y, v4.y, my);
                            mz = fmaf(w.z, v4.z, mz); mw = fmaf(w.w, v4.w, mw);
                        }
                    }
                }

                float acc = statv + relv + kprev + ((mx + my) + (mz + mw));

                // ---- deliver gates / attention scalar via st.async ----
                uint32_t boff = (uint32_t)OFF_GMB + 8u * (uint32_t)epar;
                if (role < 3) {
                    if (tid < 150) {
                        float gv = (role == 2) ? tanhf(acc) : sigf(acc);
                        uint32_t u = __float_as_uint(gv);
                        uint32_t doff = (uint32_t)OFF_GATE
                                      + (uint32_t)(epar * 480 + role * 160 + tid) * 4u;
                        st_async_b32(rb0 + doff, u, rb0 + boff);
                        st_async_b32(rb1 + doff, u, rb1 + boff);
                        st_async_b32(rb2 + doff, u, rb2 + boff);
                        st_async_b32(rb3 + doff, u, rb3 + boff);
                    }
                } else {
                    float av = (tid < 20) ? wa * tanhf(acc) : 0.f;
                    if (tid < 32) {
                        #pragma unroll
                        for (int o = 16; o; o >>= 1) av += __shfl_down_sync(0xffffffffu, av, o);
                        if (tid == 0) {
                            float a = sigf(av + ba);
                            uint32_t u = __float_as_uint(a);
                            uint32_t doff = (uint32_t)OFF_SA + 4u * (uint32_t)epar;
                            st_async_b32(rb0 + doff, u, rb0 + boff);
                            st_async_b32(rb1 + doff, u, rb1 + boff);
                            st_async_b32(rb2 + doff, u, rb2 + boff);
                            st_async_b32(rb3 + doff, u, rb3 + boff);
                        }
                    }
                }

                // ---- prefetch next edge (loads fly during the gate wait) ----
                int cnext = 0; bool cleafn = false;
                float relvn = 0.f, kprevn = 0.f;
                if (e + 1 < ee) {
                    int ce2 = __ldg(&g_echild[e + 1]);
                    cnext = ce2 & 0x7fffffff;
                    cleafn = (ce2 < 0);
                    if (role < 3) { if (comp) relvn = __ldg(&g_rel[(size_t)cnext * JPAD + role * 160 + tid]); }
                    else if (tid < 32) relvn = __ldg(&g_rel[(size_t)cnext * JPAD + 480 + tid]);
                    if (cleafn) {
                        if (role < 3) { if (comp) kprevn = __ldg(&g_kpre[(size_t)cnext * JPAD + role * 160 + tid]); }
                        else if (tid < 32) kprevn = __ldg(&g_kpre[(size_t)cnext * JPAD + 480 + tid]);
                    }
                }

                // ---- local rendezvous: wait own gate mbarrier ----
                uint32_t gmbL = base + boff;
                mbar_wait(gmbL, epar ? gph1 : gph0);
                if (epar) gph1 ^= 1; else gph0 ^= 1;

                // local combine (every CTA keeps its own h copy)
                float a = sa_sh[epar];
                if (tid < 150) {
                    const float* gb = gatebuf + epar * 480;
                    float z = gb[tid], r_ = gb[160 + tid], ht = gb[320 + tid];
                    float h = first ? 0.f : vsm[tid];
                    float m = r_ * h + (1.f - z) * ht;
                    hreg = a * m + (1.f - a) * h;
                    vsm[tid] = hreg;
                }
                __syncthreads();                   // gates consumed by all threads
                if (tid == 0) mbar_expect_tx(gmbL, GATE_TX);   // re-arm for edge+2
                if (sendNext) {                    // after first rendezvous of chain
                    int rn = atomicAdd(&g_ticket, 1);
                    uint32_t tdoff = (uint32_t)OFF_TICKBUF + 4u * (uint32_t)tslot;
                    uint32_t tboff = (uint32_t)OFF_TMB + 8u * (uint32_t)tslot;
                    st_async_b32(rb0 + tdoff, (uint32_t)rn, rb0 + tboff);
                    st_async_b32(rb1 + tdoff, (uint32_t)rn, rb1 + tboff);
                    st_async_b32(rb2 + tdoff, (uint32_t)rn, rb2 + tboff);
                    st_async_b32(rb3 + tdoff, (uint32_t)rn, rb3 + tboff);
                    sendNext = false;
                }
                first = false;
                epar ^= 1;
                c = cnext; cleaf = cleafn; relv = relvn; kprev = kprevn;
            }

            if (v == t) {                          // chain top: publish + release
                if (role == 3) {
                    if (tid < 150) g_state[v * MEM + tid] = hreg;
                    __syncthreads();               // stores done block-wide
                    if (tid == 0) st_rel(&g_child_ready[v], 1);  // release orders them
                }
                break;
            }
            // chain transition: parent consumes K[v] from registers (kcache)
            kcache = hreg;
            cache_id = v;
            v = __ldg(&g_parent_of[v]);
        }
    }
    cluster_sync2();
}

__global__ void k_out(float* __restrict__ out) {
    int m = threadIdx.x;
    if (m < MEM) out[m] = g_state[m];
}

// ---------------- launch ----------------
extern "C" void kernel_launch(void* const* d_in, const int* in_sizes, int n_in,
                              void* d_out, int out_size) {
    const float* w_emb   = (const float*)d_in[0];
    const float* tag_emb = (const float*)d_in[1];
    const float* rel_emb = (const float*)d_in[2];
    const float* leaf_h  = (const float*)d_in[3];
    const float* leaf_W  = (const float*)d_in[4];
    const float* leaf_U  = (const float*)d_in[5];
    const float* leaf_b  = (const float*)d_in[6];
    const float* node_W  = (const float*)d_in[7];
    const float* node_U  = (const float*)d_in[8];
    const float* node_b  = (const float*)d_in[9];
    const float* at_Wb   = (const float*)d_in[10];
    const float* at_bb   = (const float*)d_in[11];
    const float* at_Wa   = (const float*)d_in[12];
    const float* at_ba   = (const float*)d_in[13];
    const int*   edges   = (const int*)d_in[14];
    const int*   lids    = (const int*)d_in[15];

    int N = in_sizes[0] / 300;
    int E = in_sizes[14] / 2;
    int L = in_sizes[15];

    cudaFuncSetAttribute(k_edges, cudaFuncAttributeMaxDynamicSharedMemorySize, EDGE_SMEM);

    k_init<<<64, 256>>>(N, E);
    k_runscan<<<1, 1024>>>(edges, E);
    k_parent<<<(E + 255) / 256, 256>>>(edges, E);
    k_intlist<<<(N + 255) / 256, 256>>>(N);
    k_height<<<1, 1024>>>(N);
    k_desig2<<<(N + 255) / 256, 256>>>(N);
    k_pathscan<<<1, 1024>>>(N);
    k_build_big<<<(320 * JPAD + 255) / 256, 256>>>(node_W, node_U, at_Wb, leaf_W);
    k_build_small<<<(21 * JPAD + 255) / 256, 256>>>(node_W, at_Wb, node_b, at_bb);
    k_c0<<<1, 512>>>(leaf_U, leaf_h, leaf_b);
    k_gemm<<<dim3((N + BM - 1) / BM, JPAD / BN), 256>>>(0, N, 320, w_emb, tag_emb, lids);
    k_gemm<<<dim3((L + BM - 1) / BM, JPAD / BN), 256>>>(1, L, 320, w_emb, tag_emb, lids);
    k_relpart<<<N, 512>>>(rel_emb);
    k_leafcomb<<<(L * MEM + 255) / 256, 256>>>(lids, leaf_h, L);
    k_gemm<<<dim3((L + BM - 1) / BM, JPAD / BN), 256>>>(2, L, 160, w_emb, tag_emb, lids);
    k_edges<<<4 * NCLUST, 192, EDGE_SMEM>>>(at_Wa, at_ba);
    k_out<<<1, 256>>>((float*)d_out);
}

// round 16
// speedup vs baseline: 1.3584x; 1.3584x over previous
#include <cuda_runtime.h>
#include <cuda_bf16.h>
#include <cstdint>

#define MAXN 32768
#define MAXE 32768
#define MEM  150
#define JPAD 512
#define NCLUST 36
#define HB    32770

// ---- shared-memory byte offsets (same layout in every CTA) ----
#define OFF_GMB     0               // 2 gate mbarriers (8B each)
#define OFF_TMB     16              // 2 ticket mbarriers
#define OFF_TICKBUF 32              // 2 ints (double-buffered ticket)
#define OFF_SA      40              // 2 floats (double-buffered attention scalar)
#define OFF_GATE    64              // 2 slots * 480 floats -> [64, 3904)
#define OFF_VSM     3904            // 304 floats (h 0..151 | k 152..303), 16B aligned
#define OFF_W       5120            // h-half weights: 38*160 float4 = 97280B
#define EDGE_SMEM   (OFF_W + 38*160*16)
#define GATE_TX     1804            // 3*150*4 gate bytes + 4 bytes attention scalar

// ---------------- static device scratch (no allocations allowed) ------------
__device__ float g_state[MAXN * MEM];            // node K (published for chain tops + leaves)
__device__ float g_stat [MAXN * JPAD];           // per-node static: Ww@w + Wt@tag + bias
__device__ float g_rel  [MAXN * JPAD];           // per-node: Wrel@rel
__device__ float g_leafpre[MAXN * JPAD];         // leaf GRU pre-activations
__device__ float g_kpre [MAXN * JPAD];           // leaf nodes: Wk@K[leaf] precomputed
__device__ float g_WcombT[320 * JPAD];           // [w|tag] static weights, i-major
__device__ float g_leafWT [320 * JPAD];          // leaf_W transposed, i-major
__device__ float g_WkT   [160 * JPAD];           // k-part weights, i-major (for kpre GEMM)
__device__ float g_WrelT  [20  * JPAD];
__device__ float4 g_dyn4[76 * JPAD];             // dyn weights: vi 0..149=U(h), 152..301=Wk(k)
__device__ float g_bias[JPAD];
__device__ float g_c0[JPAD];                     // leaf: leaf_U@leaf_h + leaf_b
__device__ int   g_child_ready[MAXN];            // 0=not ready, 1=done
__device__ int   g_run_start[MAXE + 1];
__device__ int   g_run_of[MAXN];                 // node -> run id (-1 = leaf)
__device__ int   g_desig[MAXN];                  // node -> first child (chain link)
__device__ int   g_parent_of[MAXN];              // child -> parent
__device__ int   g_echild[MAXE];                 // child | (leaf << 31)
__device__ int   g_path_top[MAXE];               // chain tops (pathscan order)
__device__ int   g_path_top2[MAXE];              // chain tops, height ascending
__device__ int   g_height[MAXN];                 // subtree height (leaf = 0)
__device__ int   g_hist[HB];                     // height histogram -> offsets
__device__ int   g_internal[MAXN];               // internal node list (unordered)
__device__ int   g_NI;
__device__ int   g_P;                            // number of chains
__device__ int   g_R;
__device__ int   g_ticket;

// ---------------- asm helpers ----------------
__device__ __forceinline__ int ld_acq(const int* p) {
    int v;
    asm volatile("ld.acquire.gpu.global.b32 %0, [%1];" : "=r"(v) : "l"(p) : "memory");
    return v;
}
__device__ __forceinline__ void st_rel(int* p, int v) {
    asm volatile("st.release.gpu.global.b32 [%0], %1;" :: "l"(p), "r"(v) : "memory");
}
__device__ __forceinline__ float sigf(float x) { return 1.f / (1.f + expf(-x)); }
__device__ __forceinline__ uint32_t smem_u32(const void* p) {
    return (uint32_t)__cvta_generic_to_shared(p);
}
__device__ __forceinline__ uint32_t cluster_rank() {
    uint32_t r; asm("mov.u32 %0, %%cluster_ctarank;" : "=r"(r)); return r;
}
__device__ __forceinline__ uint32_t mapa_rank(uint32_t addr, uint32_t rank) {
    uint32_t r;
    asm("mapa.shared::cluster.u32 %0, %1, %2;" : "=r"(r) : "r"(addr), "r"(rank));
    return r;
}
__device__ __forceinline__ void mbar_init(uint32_t a, uint32_t cnt) {
    asm volatile("mbarrier.init.shared.b64 [%0], %1;" :: "r"(a), "r"(cnt) : "memory");
}
__device__ __forceinline__ void mbar_expect_tx(uint32_t a, uint32_t bytes) {
    asm volatile("mbarrier.arrive.expect_tx.shared.b64 _, [%0], %1;" :: "r"(a), "r"(bytes) : "memory");
}
__device__ __forceinline__ void st_async_b32(uint32_t remAddr, uint32_t v, uint32_t remMbar) {
    asm volatile("st.async.shared::cluster.mbarrier::complete_tx::bytes.b32 [%0], %1, [%2];"
                 :: "r"(remAddr), "r"(v), "r"(remMbar) : "memory");
}
__device__ __forceinline__ void mbar_wait(uint32_t a, uint32_t parity) {
    uint32_t done;
    do {
        asm volatile(
            "{\n\t.reg .pred p;\n\t"
            "mbarrier.try_wait.parity.acquire.cluster.shared::cta.b64 p, [%1], %2, 0x989680;\n\t"
            "selp.b32 %0, 1, 0, p;\n\t}"
            : "=r"(done) : "r"(a), "r"(parity) : "memory");
    } while (!done);
}
__device__ __forceinline__ void cluster_sync2() {
    asm volatile("barrier.cluster.arrive.aligned;" ::: "memory");
    asm volatile("barrier.cluster.wait.aligned;" ::: "memory");
}

// column -> (gru row | att row) mapping
__device__ __forceinline__ void colmap(int j, int& row, int& q) {
    row = -1; q = -1;
    if (j < 480) { int m = j % 160; if (m < 150) row = (j / 160) * 150 + m; }
    else if (j < 500) q = j - 480;
}

// ---------------- init ----------------
__global__ void k_init(int N, int E) {
    int stride = gridDim.x * blockDim.x;
    int t0 = blockIdx.x * blockDim.x + threadIdx.x;
    for (int i = t0; i < N; i += stride) { g_child_ready[i] = 0; g_run_of[i] = -1; }
    for (int i = t0; i < HB; i += stride) g_hist[i] = 0;
    if (t0 == 0) { g_ticket = 0; g_NI = 0; }
}

// ---------------- run table (single block scan) ----------------
__global__ void k_runscan(const int* __restrict__ ed, int E) {
    __shared__ int sflag[1024];
    __shared__ int sbase;
    int tid = threadIdx.x;
    if (tid == 0) sbase = 0;
    __syncthreads();
    for (int chunk = 0; chunk < E; chunk += 1024) {
        int i = chunk + tid;
        int f = 0;
        if (i < E) f = (i == 0) || (ed[2 * i] != ed[2 * i - 2]);
        sflag[tid] = f;
        __syncthreads();
        for (int off = 1; off < 1024; off <<= 1) {
            int v = (tid >= off) ? sflag[tid - off] : 0;
            __syncthreads();
            sflag[tid] += v;
            __syncthreads();
        }
        if (i < E && f) {
            int rid = sbase + sflag[tid] - 1;
            int p = ed[2 * i];
            g_run_start[rid] = i;
            g_run_of[p] = rid;
            g_desig[p] = ed[2 * i + 1];            // first child = chain link
        }
        __syncthreads();
        if (tid == 0) sbase += sflag[1023];
        __syncthreads();
    }
    if (tid == 0) { g_R = sbase; g_run_start[sbase] = E; }
}

// ---------------- parent map + packed child array + internal list -----------
__global__ void k_parent(const int* __restrict__ ed, int E) {
    int i = blockIdx.x * blockDim.x + threadIdx.x;
    if (i < E) {
        int c = ed[2 * i + 1];
        g_parent_of[c] = ed[2 * i];
        g_echild[i] = c | ((g_run_of[c] < 0) ? (int)0x80000000 : 0);
    }
    if (i == 0) g_parent_of[0] = -1;
}
__global__ void k_intlist(int N) {
    int n = blockIdx.x * blockDim.x + threadIdx.x;
    if (n < N && g_run_of[n] >= 0) g_internal[atomicAdd(&g_NI, 1)] = n;
}

// ---------------- subtree heights (one block, descending 1024-chunks) -------
// child index > parent, so deps are upward in index; higher chunks final first.
__global__ void k_height(int N) {
    __shared__ int sh[1024];
    __shared__ unsigned char sdone[1024];
    __shared__ int sleft;
    int tid = threadIdx.x;
    for (int base = ((N - 1) / 1024) * 1024; base >= 0; base -= 1024) {
        int n = base + tid;
        bool active = (n < N);
        int rid = active ? g_run_of[n] : -1;
        int es = 0, ee = 0;
        if (rid >= 0) { es = g_run_start[rid]; ee = g_run_start[rid + 1]; }
        bool done = (!active) || (rid < 0);        // leaves resolve to 0
        sh[tid] = 0;
        sdone[tid] = done ? 1 : 0;
        __syncthreads();
        while (true) {
            if (tid == 0) sleft = 0;
            __syncthreads();
            if (!done) {
                bool ok = true; int hm = 0;
                for (int e = es; e < ee; e++) {
                    int c = g_echild[e] & 0x7fffffff;
                    int hc;
                    if (c >= base && c < base + 1024) {
                        if (!sdone[c - base]) { ok = false; break; }
                        hc = sh[c - base];
                    } else {
                        hc = g_height[c];          // higher chunk, already final
                    }
                    if (hc > hm) hm = hc;
                }
                if (ok) {
                    sh[tid] = hm + 1;
                    __threadfence_block();
                    sdone[tid] = 1;
                    done = true;
                }
            }
            if (!done) atomicAdd(&sleft, 1);
            __syncthreads();
            if (sleft == 0) break;
            __syncthreads();
        }
        if (active) g_height[n] = sh[tid];
        __syncthreads();
    }
}

// ---------------- chain tops (single block scan, any order) -----------------
__global__ void k_pathscan(int N) {
    __shared__ int sflag[1024];
    __shared__ int sbase;
    int tid = threadIdx.x;
    if (tid == 0) sbase = 0;
    __syncthreads();
    for (int chunk = 0; chunk < N; chunk += 1024) {
        int nr = chunk + tid;
        int n = N - 1 - nr;
        int f = 0;
        if (nr < N && g_run_of[n] >= 0) {          // internal node
            if (n == 0) f = 1;
            else f = (g_desig[g_parent_of[n]] != n) ? 1 : 0;   // not chain-linked
        }
        sflag[tid] = f;
        __syncthreads();
        for (int off = 1; off < 1024; off <<= 1) {
            int v = (tid >= off) ? sflag[tid - off] : 0;
            __syncthreads();
            sflag[tid] += v;
            __syncthreads();
        }
        if (f) g_path_top[sbase + sflag[tid] - 1] = n;
        __syncthreads();
        if (tid == 0) sbase += sflag[1023];
        __syncthreads();
    }
    if (tid == 0) g_P = sbase;
}

// ---------------- counting sort of chain tops by height ascending -----------
__global__ void k_hist() {
    int i = blockIdx.x * blockDim.x + threadIdx.x;
    if (i < g_P) atomicAdd(&g_hist[g_height[g_path_top[i]]], 1);
}
__global__ void k_hscan() {                        // hist -> exclusive offsets
    __shared__ int s[1024];
    __shared__ int sbase;
    int tid = threadIdx.x;
    if (tid == 0) sbase = 0;
    __syncthreads();
    for (int chunk = 0; chunk < HB; chunk += 1024) {
        int i = chunk + tid;
        int v = (i < HB) ? g_hist[i] : 0;
        s[tid] = v;
        __syncthreads();
        for (int off = 1; off < 1024; off <<= 1) {
            int u = (tid >= off) ? s[tid - off] : 0;
            __syncthreads();
            s[tid] += u;
            __syncthreads();
        }
        if (i < HB) g_hist[i] = sbase + s[tid] - v;
        __syncthreads();
        if (tid == 0) sbase += s[1023];
        __syncthreads();
    }
}
__global__ void k_scatter() {
    int i = blockIdx.x * blockDim.x + threadIdx.x;
    if (i < g_P) {
        int t = g_path_top[i];
        int slot = atomicAdd(&g_hist[g_height[t]], 1);
        g_path_top2[slot] = t;
    }
}

// ---------------- weight reshuffles ----------------
// node_W: (450,490), x layout: [word 0..299 | K 300..449 | rel 450..469 | tag 470..489]
__global__ void k_build_big(const float* __restrict__ node_W, const float* __restrict__ node_U,
                            const float* __restrict__ at_Wb,  const float* __restrict__ leaf_W) {
    int idx = blockIdx.x * blockDim.x + threadIdx.x;
    if (idx >= 320 * JPAD) return;
    int i = idx / JPAD, j = idx % JPAD;
    int row, q; colmap(j, row, q);
    float v = 0.f;
    if (row >= 0)      v = (i < 300) ? node_W[row * 490 + i] : node_W[row * 490 + 470 + (i - 300)];
    else if (q >= 0)   v = (i < 300) ? at_Wb[q * 490 + i]    : at_Wb[q * 490 + 470 + (i - 300)];
    g_WcombT[idx] = v;
    g_leafWT[idx] = (row >= 0) ? leaf_W[row * 320 + i] : 0.f;
    if (i < 304) {
        float mv = 0.f;
        if (i < 150) {
            if (row >= 0) mv = node_U[row * 150 + i];
        } else if (i >= 152 && i < 302) {
            int kk = i - 152;
            if (row >= 0)      mv = node_W[row * 490 + 300 + kk];
            else if (q >= 0)   mv = at_Wb[q * 490 + 300 + kk];
        }
        reinterpret_cast<float*>(g_dyn4)[((i >> 2) * JPAD + j) * 4 + (i & 3)] = mv;
    }
    if (i < 160) {
        float kv = 0.f;
        if (i < 150) {
            if (row >= 0)      kv = node_W[row * 490 + 300 + i];
            else if (q >= 0)   kv = at_Wb[q * 490 + 300 + i];
        }
        g_WkT[i * JPAD + j] = kv;
    }
}

__global__ void k_build_small(const float* __restrict__ node_W, const float* __restrict__ at_Wb,
                              const float* __restrict__ node_b, const float* __restrict__ at_bb) {
    int idx = blockIdx.x * blockDim.x + threadIdx.x;
    if (idx < 20 * JPAD) {
        int i = idx / JPAD, j = idx % JPAD;
        int row, q; colmap(j, row, q);
        float v = 0.f;
        if (row >= 0)    v = node_W[row * 490 + 450 + i];
        else if (q >= 0) v = at_Wb[q * 490 + 450 + i];
        g_WrelT[idx] = v;
    } else if (idx < 21 * JPAD) {
        int j = idx - 20 * JPAD;
        int row, q; colmap(j, row, q);
        if (row >= 0)      g_bias[j] = node_b[row];
        else if (q >= 0)   g_bias[j] = at_bb[q];
        else               g_bias[j] = 0.f;
    }
}

__global__ void k_c0(const float* __restrict__ leaf_U, const float* __restrict__ leaf_h,
                     const float* __restrict__ leaf_b) {
    int j = threadIdx.x;
    if (j >= JPAD) return;
    int row, q; colmap(j, row, q);
    float v = 0.f;
    if (row >= 0) {
        v = leaf_b[row];
        for (int n = 0; n < MEM; n++) v += leaf_U[row * 150 + n] * leaf_h[n];
    }
    g_c0[j] = v;
}

// ---------------- tiled GEMM ----------------
// mode 0: g_stat[g_internal[r]][j] = [w|tag] @ WcombT + bias (M=g_NI, K=320)
// mode 1: g_leafpre[l][j] = [w|tag][lids[l]] @ leafWT + c0   (M=L, K=320)
// mode 2: g_kpre[lids[l]][j] = K_leaf[l] @ WkT               (M=L, K=160)
#define BM 64
#define BN 64
#define BK 16
__global__ void __launch_bounds__(256) k_gemm(int mode, int M, int Ktot,
                                              const float* __restrict__ w_emb,
                                              const float* __restrict__ tag_emb,
                                              const int* __restrict__ lids) {
    __shared__ float As[BK][BM + 4];
    __shared__ float Bs[BK][BN];
    const float* B = (mode == 0) ? g_WcombT : ((mode == 1) ? g_leafWT : g_WkT);
    const int* rmap = (mode == 0) ? g_internal : lids;
    int MM = (mode == 0) ? g_NI : M;
    int tid = threadIdx.x;
    int tx = tid & 15, ty = tid >> 4;
    int m0 = blockIdx.x * BM, j0 = blockIdx.y * BN;
    if (m0 >= MM) return;
    int ka = tid & 15, ma = tid >> 4;
    int jb = tid & 63, kb = tid >> 6;
    float acc[4][4] = {};
    for (int k0 = 0; k0 < Ktot; k0 += BK) {
        #pragma unroll
        for (int it = 0; it < 4; it++) {
            int r = m0 + ma + 16 * it;
            if (r >= MM) r = MM - 1;
            int row = rmap[r];
            int i = k0 + ka;
            float av;
            if (mode == 2) av = (i < 150) ? g_state[row * MEM + i] : 0.f;
            else av = (i < 300) ? w_emb[row * 300 + i] : tag_emb[row * 20 + (i - 300)];
            As[ka][ma + 16 * it] = av;
        }
        #pragma unroll
        for (int it = 0; it < 4; it++)
            Bs[kb + 4 * it][jb] = B[(k0 + kb + 4 * it) * JPAD + (j0 + jb)];
        __syncthreads();
        #pragma unroll
        for (int k = 0; k < BK; k++) {
            float4 a4 = *(const float4*)&As[k][ty * 4];
            float4 b4 = *(const float4*)&Bs[k][tx * 4];
            float av[4] = {a4.x, a4.y, a4.z, a4.w};
            float bv[4] = {b4.x, b4.y, b4.z, b4.w};
            #pragma unroll
            for (int mm = 0; mm < 4; mm++)
                #pragma unroll
                for (int jj = 0; jj < 4; jj++)
                    acc[mm][jj] = fmaf(av[mm], bv[jj], acc[mm][jj]);
        }
        __syncthreads();
    }
    #pragma unroll
    for (int mm = 0; mm < 4; mm++) {
        int r = m0 + ty * 4 + mm;
        if (r >= MM) continue;
        #pragma unroll
        for (int jj = 0; jj < 4; jj++) {
            int j = j0 + tx * 4 + jj;
            int row = rmap[r];
            if (mode == 0)      g_stat[(size_t)row * JPAD + j] = acc[mm][jj] + g_bias[j];
            else if (mode == 1) g_leafpre[(size_t)r * JPAD + j] = acc[mm][jj] + g_c0[j];
            else                g_kpre[(size_t)row * JPAD + j] = acc[mm][jj];
        }
    }
}

// ---------------- rel projection (K=20) ----------------
__global__ void __launch_bounds__(512) k_relpart(const float* __restrict__ rel_emb) {
    int n = blockIdx.x, j = threadIdx.x;
    float acc = 0.f;
    #pragma unroll
    for (int q = 0; q < 20; q++)
        acc = fmaf(g_WrelT[q * JPAD + j], __ldg(&rel_emb[n * 20 + q]), acc);
    g_rel[n * JPAD + j] = acc;
}

// ---------------- leaf epilogue ----------------
__global__ void k_leafcomb(const int* __restrict__ lids, const float* __restrict__ leaf_h, int L) {
    int idx = blockIdx.x * blockDim.x + threadIdx.x;
    if (idx >= L * MEM) return;
    int l = idx / MEM, m = idx % MEM;
    float z  = sigf (g_leafpre[l * JPAD + m]);
    float r  = sigf (g_leafpre[l * JPAD + 160 + m]);
    float ht = tanhf(g_leafpre[l * JPAD + 320 + m]);
    g_state[lids[l] * MEM + m] = r * leaf_h[m] + (1.f - z) * ht;
}

// ---------------- persistent cluster-4 chain kernel -------------------------
// First-child chains, tickets ordered by subtree height ASCENDING (wavefront).
// roles 0/1/2: z/r/ht gate CTAs (160 cols); role 3: attention (32 cols)
// k-half weights in REGISTERS; h-half in SMEM; 4-way split accumulators.
// warp 5 (tid 160) = dedicated dependency poller, overlaps h-matvec.
__global__ void __launch_bounds__(192, 1) __cluster_dims__(4, 1, 1)
k_edges(const float* __restrict__ at_Wa, const float* __restrict__ at_ba) {
    extern __shared__ char smem[];
    volatile int*   tickbuf = (volatile int*)(smem + OFF_TICKBUF);
    volatile float* sa_sh   = (volatile float*)(smem + OFF_SA);
    float*  gatebuf = (float*)(smem + OFF_GATE);   // [2][480]
    float*  vsm  = (float*)(smem + OFF_VSM);
    float4* vsm4 = (float4*)vsm;
    float4* sw4  = (float4*)(smem + OFF_W);        // h-half weights only (rows 0..37)
    uint32_t base = smem_u32(smem);

    int tid = threadIdx.x;
    int role = (int)cluster_rank();
    bool comp = (tid < 160);

    // k-half weights in registers
    float4 wk[38];
    if (role < 3) {
        if (comp) {
            int j0 = role * 160;
            #pragma unroll
            for (int r = 0; r < 38; r++) {
                sw4[r * 160 + tid] = g_dyn4[r * JPAD + j0 + tid];          // h rows
                wk[r] = g_dyn4[(38 + r) * JPAD + j0 + tid];                // k rows
            }
        }
    } else if (tid < 32) {
        #pragma unroll
        for (int r = 0; r < 38; r++)
            wk[r] = g_dyn4[(38 + r) * JPAD + 480 + tid];
    }
    if (tid < 4) vsm[150 + (tid >> 1) * 152 + (tid & 1)] = 0.f;  // pads 150,151,302,303
    __syncthreads();

    if (tid == 0) {
        mbar_init(base + OFF_GMB, 1);      mbar_init(base + OFF_GMB + 8, 1);
        mbar_init(base + OFF_TMB, 1);      mbar_init(base + OFF_TMB + 8, 1);
    }
    __syncthreads();
    if (tid == 0) {
        mbar_expect_tx(base + OFF_GMB,     GATE_TX);
        mbar_expect_tx(base + OFF_GMB + 8, GATE_TX);
        mbar_expect_tx(base + OFF_TMB,     4);
        mbar_expect_tx(base + OFF_TMB + 8, 4);
    }
    __syncthreads();

    uint32_t rb0 = mapa_rank(base, 0), rb1 = mapa_rank(base, 1);
    uint32_t rb2 = mapa_rank(base, 2), rb3 = mapa_rank(base, 3);

    float ba = 0.f, wa = 0.f;
    if (role == 3) { ba = *at_ba; wa = (tid < 20) ? at_Wa[tid] : 0.f; }

    cluster_sync2();                               // all barriers armed cluster-wide

    if (role == 0 && tid == 0) {                   // bootstrap ticket -> slot 0
        int e0 = atomicAdd(&g_ticket, 1);
        st_async_b32(rb0 + OFF_TICKBUF, (uint32_t)e0, rb0 + OFF_TMB);
        st_async_b32(rb1 + OFF_TICKBUF, (uint32_t)e0, rb1 + OFF_TMB);
        st_async_b32(rb2 + OFF_TICKBUF, (uint32_t)e0, rb2 + OFF_TMB);
        st_async_b32(rb3 + OFF_TICKBUF, (uint32_t)e0, rb3 + OFF_TMB);
    }

    int P = g_P;
    int epar = 0;
    uint32_t gph0 = 0, gph1 = 0;
    int tslot = 0; uint32_t tph0 = 0, tph1 = 0;

    while (true) {
        // ---- ticket rendezvous ----
        uint32_t tmbL = base + OFF_TMB + 8u * (uint32_t)tslot;
        mbar_wait(tmbL, tslot ? tph1 : tph0);
        if (tslot) tph1 ^= 1; else tph0 ^= 1;
        int r = tickbuf[tslot];
        __syncthreads();                           // all read before re-arm
        if (tid == 0) mbar_expect_tx(tmbL, 4);
        if (r >= P) break;
        bool sendNext = (role == 0 && tid == 0);
        tslot ^= 1;

        int t = __ldg(&g_path_top2[r]);
        int v = t;
        while (true) {
            int d = __ldg(&g_desig[v]);
            if (__ldg(&g_run_of[d]) < 0) break;
            v = d;
        }
        int cache_id = -1;

        while (true) {                             // chain bottom-up
            int rid = __ldg(&g_run_of[v]);
            int es = __ldg(&g_run_start[rid]), ee = __ldg(&g_run_start[rid + 1]);

            float statv = 0.f;
            if (role < 3) { if (comp) statv = __ldg(&g_stat[(size_t)v * JPAD + role * 160 + tid]); }
            else if (tid < 32) statv = __ldg(&g_stat[(size_t)v * JPAD + 480 + tid]);

            // prefetch first edge of run
            int ce = __ldg(&g_echild[es]);
            int c = ce & 0x7fffffff;
            bool cleaf = (ce < 0);
            float relv = 0.f, kprev = 0.f;
            if (role < 3) { if (comp) relv = __ldg(&g_rel[(size_t)c * JPAD + role * 160 + tid]); }
            else if (tid < 32) relv = __ldg(&g_rel[(size_t)c * JPAD + 480 + tid]);
            if (cleaf) {
                if (role < 3) { if (comp) kprev = __ldg(&g_kpre[(size_t)c * JPAD + role * 160 + tid]); }
                else if (tid < 32) kprev = __ldg(&g_kpre[(size_t)c * JPAD + 480 + tid]);
            }

            bool first = true;
            float hreg = 0.f;

            for (int e = es; e < ee; e++) {
                bool cached = (c == cache_id);
                float mx = 0.f, my = 0.f, mz = 0.f, mw = 0.f;   // 4 split accumulators

                // dedicated poller (warp 5) overlaps the h-matvec below
                if (tid == 160 && !cleaf && !cached) {
                    int n = 0;
                    while (!ld_acq(&g_child_ready[c])) { if (++n > 256) __nanosleep(32); }
                }
                if (!first && role < 3 && comp) {
                    const float4* wp = sw4 + tid;
                    #pragma unroll 4
                    for (int r2 = 0; r2 < 38; r2++) {
                        float4 w = wp[r2 * 160]; float4 v4 = vsm4[r2];
                        mx = fmaf(w.x, v4.x, mx); my = fmaf(w.y, v4.y, my);
                        mz = fmaf(w.z, v4.z, mz); mw = fmaf(w.w, v4.w, mw);
                    }
                }
                __syncthreads();                   // join poll + h-matvec

                if (!cleaf) {
                    if (!cached) {
                        if (tid < 150) vsm[152 + tid] = __ldcg(&g_state[c * MEM + tid]);
                        __syncthreads();
                    }
                    if ((role < 3 && comp) || (role == 3 && tid < 32)) {
                        #pragma unroll 4
                        for (int r2 = 0; r2 < 38; r2++) {
                            float4 w = wk[r2]; float4 v4 = vsm4[38 + r2];
                            mx = fmaf(w.x, v4.x, mx); my = fmaf(w.y, v4.y, my);
                            mz = fmaf(w.z, v4.z, mz); mw = fmaf(w.w, v4.w, mw);
                        }
                    }
                }

                float acc = statv + relv + kprev + ((mx + my) + (mz + mw));

                // ---- deliver gates / attention scalar via st.async ----
                uint32_t boff = (uint32_t)OFF_GMB + 8u * (uint32_t)epar;
                if (role < 3) {
                    if (tid < 150) {
                        float gv = (role == 2) ? tanhf(acc) : sigf(acc);
                        uint32_t u = __float_as_uint(gv);
                        uint32_t doff = (uint32_t)OFF_GATE
                                      + (uint32_t)(epar * 480 + role * 160 + tid) * 4u;
                        st_async_b32(rb0 + doff, u, rb0 + boff);
                        st_async_b32(rb1 + doff, u, rb1 + boff);
                        st_async_b32(rb2 + doff, u, rb2 + boff);
                        st_async_b32(rb3 + doff, u, rb3 + boff);
                    }
                } else {
                    float av = (tid < 20) ? wa * tanhf(acc) : 0.f;
                    if (tid < 32) {
                        #pragma unroll
                        for (int o = 16; o; o >>= 1) av += __shfl_down_sync(0xffffffffu, av, o);
                        if (tid == 0) {
                            float a = sigf(av + ba);
                            uint32_t u = __float_as_uint(a);
                            uint32_t doff = (uint32_t)OFF_SA + 4u * (uint32_t)epar;
                            st_async_b32(rb0 + doff, u, rb0 + boff);
                            st_async_b32(rb1 + doff, u, rb1 + boff);
                            st_async_b32(rb2 + doff, u, rb2 + boff);
                            st_async_b32(rb3 + doff, u, rb3 + boff);
                        }
                    }
                }

                // ---- prefetch next edge (loads fly during the gate wait) ----
                int cnext = 0; bool cleafn = false;
                float relvn = 0.f, kprevn = 0.f;
                if (e + 1 < ee) {
                    int ce2 = __ldg(&g_echild[e + 1]);
                    cnext = ce2 & 0x7fffffff;
                    cleafn = (ce2 < 0);
                    if (role < 3) { if (comp) relvn = __ldg(&g_rel[(size_t)cnext * JPAD + role * 160 + tid]); }
                    else if (tid < 32) relvn = __ldg(&g_rel[(size_t)cnext * JPAD + 480 + tid]);
                    if (cleafn) {
                        if (role < 3) { if (comp) kprevn = __ldg(&g_kpre[(size_t)cnext * JPAD + role * 160 + tid]); }
                        else if (tid < 32) kprevn = __ldg(&g_kpre[(size_t)cnext * JPAD + 480 + tid]);
                    }
                }

                // ---- local rendezvous: wait own gate mbarrier ----
                uint32_t gmbL = base + boff;
                mbar_wait(gmbL, epar ? gph1 : gph0);
                if (epar) gph1 ^= 1; else gph0 ^= 1;

                // local combine (every CTA keeps its own h copy)
                float a = sa_sh[epar];
                if (tid < 150) {
                    const float* gb = gatebuf + epar * 480;
                    float z = gb[tid], r_ = gb[160 + tid], ht = gb[320 + tid];
                    float h = first ? 0.f : vsm[tid];
                    float m = r_ * h + (1.f - z) * ht;
                    hreg = a * m + (1.f - a) * h;
                    vsm[tid] = hreg;
                }
                __syncthreads();                   // gates consumed by all threads
                if (tid == 0) mbar_expect_tx(gmbL, GATE_TX);   // re-arm for edge+2
                if (sendNext) {                    // after first rendezvous of chain
                    int rn = atomicAdd(&g_ticket, 1);
                    uint32_t tdoff = (uint32_t)OFF_TICKBUF + 4u * (uint32_t)tslot;
                    uint32_t tboff = (uint32_t)OFF_TMB + 8u * (uint32_t)tslot;
                    st_async_b32(rb0 + tdoff, (uint32_t)rn, rb0 + tboff);
                    st_async_b32(rb1 + tdoff, (uint32_t)rn, rb1 + tboff);
                    st_async_b32(rb2 + tdoff, (uint32_t)rn, rb2 + tboff);
                    st_async_b32(rb3 + tdoff, (uint32_t)rn, rb3 + tboff);
                    sendNext = false;
                }
                first = false;
                epar ^= 1;
                c = cnext; cleaf = cleafn; relv = relvn; kprev = kprevn;
            }

            if (v == t) {                          // chain top: publish + release
                if (role == 3) {
                    if (tid < 150) g_state[v * MEM + tid] = hreg;
                    __syncthreads();               // stores done block-wide
                    if (tid == 0) st_rel(&g_child_ready[v], 1);  // release orders them
                }
                break;
            }
            // chain transition: parent's first edge consumes K[v] from SMEM
            if (tid < 150) vsm[152 + tid] = hreg;
            __syncthreads();
            cache_id = v;
            v = __ldg(&g_parent_of[v]);
        }
    }
    cluster_sync2();
}

__global__ void k_out(float* __restrict__ out) {
    int m = threadIdx.x;
    if (m < MEM) out[m] = g_state[m];
}

// ---------------- launch ----------------
extern "C" void kernel_launch(void* const* d_in, const int* in_sizes, int n_in,
                              void* d_out, int out_size) {
    const float* w_emb   = (const float*)d_in[0];
    const float* tag_emb = (const float*)d_in[1];
    const float* rel_emb = (const float*)d_in[2];
    const float* leaf_h  = (const float*)d_in[3];
    const float* leaf_W  = (const float*)d_in[4];
    const float* leaf_U  = (const float*)d_in[5];
    const float* leaf_b  = (const float*)d_in[6];
    const float* node_W  = (const float*)d_in[7];
    const float* node_U  = (const float*)d_in[8];
    const float* node_b  = (const float*)d_in[9];
    const float* at_Wb   = (const float*)d_in[10];
    const float* at_bb   = (const float*)d_in[11];
    const float* at_Wa   = (const float*)d_in[12];
    const float* at_ba   = (const float*)d_in[13];
    const int*   edges   = (const int*)d_in[14];
    const int*   lids    = (const int*)d_in[15];

    int N = in_sizes[0] / 300;
    int E = in_sizes[14] / 2;
    int L = in_sizes[15];

    cudaFuncSetAttribute(k_edges, cudaFuncAttributeMaxDynamicSharedMemorySize, EDGE_SMEM);

    k_init<<<64, 256>>>(N, E);
    k_runscan<<<1, 1024>>>(edges, E);
    k_parent<<<(E + 255) / 256, 256>>>(edges, E);
    k_intlist<<<(N + 255) / 256, 256>>>(N);
    k_height<<<1, 1024>>>(N);
    k_pathscan<<<1, 1024>>>(N);
    k_hist<<<(MAXE + 255) / 256, 256>>>();
    k_hscan<<<1, 1024>>>();
    k_scatter<<<(MAXE + 255) / 256, 256>>>();
    k_build_big<<<(320 * JPAD + 255) / 256, 256>>>(node_W, node_U, at_Wb, leaf_W);
    k_build_small<<<(21 * JPAD + 255) / 256, 256>>>(node_W, at_Wb, node_b, at_bb);
    k_c0<<<1, 512>>>(leaf_U, leaf_h, leaf_b);
    k_gemm<<<dim3((N + BM - 1) / BM, JPAD / BN), 256>>>(0, N, 320, w_emb, tag_emb, lids);
    k_gemm<<<dim3((L + BM - 1) / BM, JPAD / BN), 256>>>(1, L, 320, w_emb, tag_emb, lids);
    k_relpart<<<N, 512>>>(rel_emb);
    k_leafcomb<<<(L * MEM + 255) / 256, 256>>>(lids, leaf_h, L);
    k_gemm<<<dim3((L + BM - 1) / BM, JPAD / BN), 256>>>(2, L, 160, w_emb, tag_emb, lids);
    k_edges<<<4 * NCLUST, 192, EDGE_SMEM>>>(at_Wa, at_ba);
    k_out<<<1, 256>>>((float*)d_out);
}

// round 17
// speedup vs baseline: 1.5434x; 1.1362x over previous
#include <cuda_runtime.h>
#include <cuda_bf16.h>
#include <cstdint>

#define MAXN 32768
#define MAXE 32768
#define MEM  150
#define JPAD 512
#define NCLUST 36

// ---- shared-memory byte offsets (same layout in every CTA) ----
#define OFF_GMB     0               // 2 gate mbarriers (8B each)
#define OFF_TMB     16              // 2 ticket mbarriers
#define OFF_TICKBUF 32              // 2 ints (double-buffered ticket)
#define OFF_SA      40              // 2 floats (double-buffered attention scalar)
#define OFF_GATE    64              // 2 slots * 480 floats -> [64, 3904)
#define OFF_VSM     3904            // 304 floats (h 0..151 | k 152..303), 16B aligned
#define OFF_PBUF    5120            // 160 floats partial-sum buffer -> [5120, 5760)
#define OFF_W       5760            // full dyn weights: 76*160 float4 = 194560B
#define EDGE_SMEM   (OFF_W + 76*160*16)
#define GATE_TX     1804            // 3*150*4 gate bytes + 4 bytes attention scalar

// ---------------- static device scratch (no allocations allowed) ------------
__device__ float g_state[MAXN * MEM];            // node K (published for chain tops + leaves)
__device__ float g_stat [MAXN * JPAD];           // per-node static: Ww@w + Wt@tag + bias
__device__ float g_rel  [MAXN * JPAD];           // per-node: Wrel@rel
__device__ float g_leafpre[MAXN * JPAD];         // leaf GRU pre-activations
__device__ float g_kpre [MAXN * JPAD];           // leaf nodes: Wk@K[leaf] precomputed
__device__ float g_WcombT[320 * JPAD];           // [w|tag] static weights, i-major
__device__ float g_leafWT [320 * JPAD];          // leaf_W transposed, i-major
__device__ float g_WkT   [160 * JPAD];           // k-part weights, i-major (for kpre GEMM)
__device__ float g_WrelT  [20  * JPAD];
__device__ float4 g_dyn4[76 * JPAD];             // dyn weights: vi 0..149=U(h), 152..301=Wk(k)
__device__ float g_bias[JPAD];
__device__ float g_c0[JPAD];                     // leaf: leaf_U@leaf_h + leaf_b
__device__ int   g_child_ready[MAXN];            // 0=not ready, 1=done
__device__ int   g_run_start[MAXE + 1];
__device__ int   g_run_of[MAXN];                 // node -> run id (-1 = leaf)
__device__ int   g_desig[MAXN];                  // node -> first child (chain link)
__device__ int   g_parent_of[MAXN];              // child -> parent
__device__ int   g_echild[MAXE];                 // child | (leaf << 31)
__device__ int   g_path_top[MAXE];               // chain tops, node index descending
__device__ int   g_internal[MAXN];               // internal node list (unordered)
__device__ int   g_NI;
__device__ int   g_P;                            // number of chains
__device__ int   g_R;
__device__ int   g_ticket;

// ---------------- asm helpers ----------------
__device__ __forceinline__ int ld_acq(const int* p) {
    int v;
    asm volatile("ld.acquire.gpu.global.b32 %0, [%1];" : "=r"(v) : "l"(p) : "memory");
    return v;
}
__device__ __forceinline__ void st_rel(int* p, int v) {
    asm volatile("st.release.gpu.global.b32 [%0], %1;" :: "l"(p), "r"(v) : "memory");
}
__device__ __forceinline__ float sigf(float x) { return 1.f / (1.f + expf(-x)); }
__device__ __forceinline__ uint32_t smem_u32(const void* p) {
    return (uint32_t)__cvta_generic_to_shared(p);
}
__device__ __forceinline__ uint32_t cluster_rank() {
    uint32_t r; asm("mov.u32 %0, %%cluster_ctarank;" : "=r"(r)); return r;
}
__device__ __forceinline__ uint32_t mapa_rank(uint32_t addr, uint32_t rank) {
    uint32_t r;
    asm("mapa.shared::cluster.u32 %0, %1, %2;" : "=r"(r) : "r"(addr), "r"(rank));
    return r;
}
__device__ __forceinline__ void mbar_init(uint32_t a, uint32_t cnt) {
    asm volatile("mbarrier.init.shared.b64 [%0], %1;" :: "r"(a), "r"(cnt) : "memory");
}
__device__ __forceinline__ void mbar_expect_tx(uint32_t a, uint32_t bytes) {
    asm volatile("mbarrier.arrive.expect_tx.shared.b64 _, [%0], %1;" :: "r"(a), "r"(bytes) : "memory");
}
__device__ __forceinline__ void st_async_b32(uint32_t remAddr, uint32_t v, uint32_t remMbar) {
    asm volatile("st.async.shared::cluster.mbarrier::complete_tx::bytes.b32 [%0], %1, [%2];"
                 :: "r"(remAddr), "r"(v), "r"(remMbar) : "memory");
}
__device__ __forceinline__ void mbar_wait(uint32_t a, uint32_t parity) {
    uint32_t done;
    do {
        asm volatile(
            "{\n\t.reg .pred p;\n\t"
            "mbarrier.try_wait.parity.acquire.cluster.shared::cta.b64 p, [%1], %2, 0x989680;\n\t"
            "selp.b32 %0, 1, 0, p;\n\t}"
            : "=r"(done) : "r"(a), "r"(parity) : "memory");
    } while (!done);
}
__device__ __forceinline__ void cluster_sync2() {
    asm volatile("barrier.cluster.arrive.aligned;" ::: "memory");
    asm volatile("barrier.cluster.wait.aligned;" ::: "memory");
}

// column -> (gru row | att row) mapping
__device__ __forceinline__ void colmap(int j, int& row, int& q) {
    row = -1; q = -1;
    if (j < 480) { int m = j % 160; if (m < 150) row = (j / 160) * 150 + m; }
    else if (j < 500) q = j - 480;
}

// ---------------- init ----------------
__global__ void k_init(int N, int E) {
    int stride = gridDim.x * blockDim.x;
    int t0 = blockIdx.x * blockDim.x + threadIdx.x;
    for (int i = t0; i < N; i += stride) { g_child_ready[i] = 0; g_run_of[i] = -1; }
    if (t0 == 0) { g_ticket = 0; g_NI = 0; }
}

// ---------------- run table (single block scan) ----------------
__global__ void k_runscan(const int* __restrict__ ed, int E) {
    __shared__ int sflag[1024];
    __shared__ int sbase;
    int tid = threadIdx.x;
    if (tid == 0) sbase = 0;
    __syncthreads();
    for (int chunk = 0; chunk < E; chunk += 1024) {
        int i = chunk + tid;
        int f = 0;
        if (i < E) f = (i == 0) || (ed[2 * i] != ed[2 * i - 2]);
        sflag[tid] = f;
        __syncthreads();
        for (int off = 1; off < 1024; off <<= 1) {
            int v = (tid >= off) ? sflag[tid - off] : 0;
            __syncthreads();
            sflag[tid] += v;
            __syncthreads();
        }
        if (i < E && f) {
            int rid = sbase + sflag[tid] - 1;
            int p = ed[2 * i];
            g_run_start[rid] = i;
            g_run_of[p] = rid;
            g_desig[p] = ed[2 * i + 1];            // first child = chain link
        }
        __syncthreads();
        if (tid == 0) sbase += sflag[1023];
        __syncthreads();
    }
    if (tid == 0) { g_R = sbase; g_run_start[sbase] = E; }
}

// ---------------- parent map + packed child array + internal list -----------
__global__ void k_parent(const int* __restrict__ ed, int E) {
    int i = blockIdx.x * blockDim.x + threadIdx.x;
    if (i < E) {
        int c = ed[2 * i + 1];
        g_parent_of[c] = ed[2 * i];
        g_echild[i] = c | ((g_run_of[c] < 0) ? (int)0x80000000 : 0);
    }
    if (i == 0) g_parent_of[0] = -1;
}
__global__ void k_intlist(int N) {
    int n = blockIdx.x * blockDim.x + threadIdx.x;
    if (n < N && g_run_of[n] >= 0) g_internal[atomicAdd(&g_NI, 1)] = n;
}

// ---------------- chain tops, node index descending (single block scan) -----
__global__ void k_pathscan(int N) {
    __shared__ int sflag[1024];
    __shared__ int sbase;
    int tid = threadIdx.x;
    if (tid == 0) sbase = 0;
    __syncthreads();
    for (int chunk = 0; chunk < N; chunk += 1024) {
        int nr = chunk + tid;
        int n = N - 1 - nr;
        int f = 0;
        if (nr < N && g_run_of[n] >= 0) {          // internal node
            if (n == 0) f = 1;
            else f = (g_desig[g_parent_of[n]] != n) ? 1 : 0;   // not chain-linked
        }
        sflag[tid] = f;
        __syncthreads();
        for (int off = 1; off < 1024; off <<= 1) {
            int v = (tid >= off) ? sflag[tid - off] : 0;
            __syncthreads();
            sflag[tid] += v;
            __syncthreads();
        }
        if (f) g_path_top[sbase + sflag[tid] - 1] = n;
        __syncthreads();
        if (tid == 0) sbase += sflag[1023];
        __syncthreads();
    }
    if (tid == 0) g_P = sbase;
}

// ---------------- weight reshuffles ----------------
// node_W: (450,490), x layout: [word 0..299 | K 300..449 | rel 450..469 | tag 470..489]
__global__ void k_build_big(const float* __restrict__ node_W, const float* __restrict__ node_U,
                            const float* __restrict__ at_Wb,  const float* __restrict__ leaf_W) {
    int idx = blockIdx.x * blockDim.x + threadIdx.x;
    if (idx >= 320 * JPAD) return;
    int i = idx / JPAD, j = idx % JPAD;
    int row, q; colmap(j, row, q);
    float v = 0.f;
    if (row >= 0)      v = (i < 300) ? node_W[row * 490 + i] : node_W[row * 490 + 470 + (i - 300)];
    else if (q >= 0)   v = (i < 300) ? at_Wb[q * 490 + i]    : at_Wb[q * 490 + 470 + (i - 300)];
    g_WcombT[idx] = v;
    g_leafWT[idx] = (row >= 0) ? leaf_W[row * 320 + i] : 0.f;
    if (i < 304) {
        float mv = 0.f;
        if (i < 150) {
            if (row >= 0) mv = node_U[row * 150 + i];
        } else if (i >= 152 && i < 302) {
            int kk = i - 152;
            if (row >= 0)      mv = node_W[row * 490 + 300 + kk];
            else if (q >= 0)   mv = at_Wb[q * 490 + 300 + kk];
        }
        reinterpret_cast<float*>(g_dyn4)[((i >> 2) * JPAD + j) * 4 + (i & 3)] = mv;
    }
    if (i < 160) {
        float kv = 0.f;
        if (i < 150) {
            if (row >= 0)      kv = node_W[row * 490 + 300 + i];
            else if (q >= 0)   kv = at_Wb[q * 490 + 300 + i];
        }
        g_WkT[i * JPAD + j] = kv;
    }
}

__global__ void k_build_small(const float* __restrict__ node_W, const float* __restrict__ at_Wb,
                              const float* __restrict__ node_b, const float* __restrict__ at_bb) {
    int idx = blockIdx.x * blockDim.x + threadIdx.x;
    if (idx < 20 * JPAD) {
        int i = idx / JPAD, j = idx % JPAD;
        int row, q; colmap(j, row, q);
        float v = 0.f;
        if (row >= 0)    v = node_W[row * 490 + 450 + i];
        else if (q >= 0) v = at_Wb[q * 490 + 450 + i];
        g_WrelT[idx] = v;
    } else if (idx < 21 * JPAD) {
        int j = idx - 20 * JPAD;
        int row, q; colmap(j, row, q);
        if (row >= 0)      g_bias[j] = node_b[row];
        else if (q >= 0)   g_bias[j] = at_bb[q];
        else               g_bias[j] = 0.f;
    }
}

__global__ void k_c0(const float* __restrict__ leaf_U, const float* __restrict__ leaf_h,
                     const float* __restrict__ leaf_b) {
    int j = threadIdx.x;
    if (j >= JPAD) return;
    int row, q; colmap(j, row, q);
    float v = 0.f;
    if (row >= 0) {
        v = leaf_b[row];
        for (int n = 0; n < MEM; n++) v += leaf_U[row * 150 + n] * leaf_h[n];
    }
    g_c0[j] = v;
}

// ---------------- tiled GEMM ----------------
// mode 0: g_stat[g_internal[r]][j] = [w|tag] @ WcombT + bias (M=g_NI, K=320)
// mode 1: g_leafpre[l][j] = [w|tag][lids[l]] @ leafWT + c0   (M=L, K=320)
// mode 2: g_kpre[lids[l]][j] = K_leaf[l] @ WkT               (M=L, K=160)
#define BM 64
#define BN 64
#define BK 16
__global__ void __launch_bounds__(256) k_gemm(int mode, int M, int Ktot,
                                              const float* __restrict__ w_emb,
                                              const float* __restrict__ tag_emb,
                                              const int* __restrict__ lids) {
    __shared__ float As[BK][BM + 4];
    __shared__ float Bs[BK][BN];
    const float* B = (mode == 0) ? g_WcombT : ((mode == 1) ? g_leafWT : g_WkT);
    const int* rmap = (mode == 0) ? g_internal : lids;
    int MM = (mode == 0) ? g_NI : M;
    int tid = threadIdx.x;
    int tx = tid & 15, ty = tid >> 4;
    int m0 = blockIdx.x * BM, j0 = blockIdx.y * BN;
    if (m0 >= MM) return;
    int ka = tid & 15, ma = tid >> 4;
    int jb = tid & 63, kb = tid >> 6;
    float acc[4][4] = {};
    for (int k0 = 0; k0 < Ktot; k0 += BK) {
        #pragma unroll
        for (int it = 0; it < 4; it++) {
            int r = m0 + ma + 16 * it;
            if (r >= MM) r = MM - 1;
            int row = rmap[r];
            int i = k0 + ka;
            float av;
            if (mode == 2) av = (i < 150) ? g_state[row * MEM + i] : 0.f;
            else av = (i < 300) ? w_emb[row * 300 + i] : tag_emb[row * 20 + (i - 300)];
            As[ka][ma + 16 * it] = av;
        }
        #pragma unroll
        for (int it = 0; it < 4; it++)
            Bs[kb + 4 * it][jb] = B[(k0 + kb + 4 * it) * JPAD + (j0 + jb)];
        __syncthreads();
        #pragma unroll
        for (int k = 0; k < BK; k++) {
            float4 a4 = *(const float4*)&As[k][ty * 4];
            float4 b4 = *(const float4*)&Bs[k][tx * 4];
            float av[4] = {a4.x, a4.y, a4.z, a4.w};
            float bv[4] = {b4.x, b4.y, b4.z, b4.w};
            #pragma unroll
            for (int mm = 0; mm < 4; mm++)
                #pragma unroll
                for (int jj = 0; jj < 4; jj++)
                    acc[mm][jj] = fmaf(av[mm], bv[jj], acc[mm][jj]);
        }
        __syncthreads();
    }
    #pragma unroll
    for (int mm = 0; mm < 4; mm++) {
        int r = m0 + ty * 4 + mm;
        if (r >= MM) continue;
        #pragma unroll
        for (int jj = 0; jj < 4; jj++) {
            int j = j0 + tx * 4 + jj;
            int row = rmap[r];
            if (mode == 0)      g_stat[(size_t)row * JPAD + j] = acc[mm][jj] + g_bias[j];
            else if (mode == 1) g_leafpre[(size_t)r * JPAD + j] = acc[mm][jj] + g_c0[j];
            else                g_kpre[(size_t)row * JPAD + j] = acc[mm][jj];
        }
    }
}

// ---------------- rel projection (K=20) ----------------
__global__ void __launch_bounds__(512) k_relpart(const float* __restrict__ rel_emb) {
    int n = blockIdx.x, j = threadIdx.x;
    float acc = 0.f;
    #pragma unroll
    for (int q = 0; q < 20; q++)
        acc = fmaf(g_WrelT[q * JPAD + j], __ldg(&rel_emb[n * 20 + q]), acc);
    g_rel[n * JPAD + j] = acc;
}

// ---------------- leaf epilogue ----------------
__global__ void k_leafcomb(const int* __restrict__ lids, const float* __restrict__ leaf_h, int L) {
    int idx = blockIdx.x * blockDim.x + threadIdx.x;
    if (idx >= L * MEM) return;
    int l = idx / MEM, m = idx % MEM;
    float z  = sigf (g_leafpre[l * JPAD + m]);
    float r  = sigf (g_leafpre[l * JPAD + 160 + m]);
    float ht = tanhf(g_leafpre[l * JPAD + 320 + m]);
    g_state[lids[l] * MEM + m] = r * leaf_h[m] + (1.f - z) * ht;
}

// ---------------- persistent cluster-4 chain kernel -------------------------
// R14 engine (first-child chains, index-descending tickets) with ROW-SPLIT
// matvecs: 2 threads per output column (19 float4-rows each), partials joined
// via SMEM. Workers: 320 compute threads (160 cols x 2); role3: 64 (32 x 2).
// Thread 320 = dedicated dependency poller.
__global__ void __launch_bounds__(352, 1) __cluster_dims__(4, 1, 1)
k_edges(const float* __restrict__ at_Wa, const float* __restrict__ at_ba) {
    extern __shared__ char smem[];
    volatile int*   tickbuf = (volatile int*)(smem + OFF_TICKBUF);
    volatile float* sa_sh   = (volatile float*)(smem + OFF_SA);
    float*  gatebuf = (float*)(smem + OFF_GATE);   // [2][480]
    float*  vsm  = (float*)(smem + OFF_VSM);
    float*  pbuf = (float*)(smem + OFF_PBUF);      // 160 partials
    float4* vsm4 = (float4*)vsm;
    float4* sw4  = (float4*)(smem + OFF_W);
    uint32_t base = smem_u32(smem);

    int tid = threadIdx.x;
    int role = (int)cluster_rank();
    bool isw   = (role < 3) && (tid < 320);        // worker compute thread
    bool isa   = (role == 3) && (tid < 64);        // attention compute thread
    bool lowW  = (role < 3) && (tid < 160);
    bool lowA  = (role == 3) && (tid < 32);
    int  col   = (role < 3) ? (tid % 160) : (tid & 31);
    int  rh    = (role < 3) ? ((tid < 160) ? 0 : 19) : ((tid < 32) ? 0 : 19);

    // weights into SMEM
    if (role < 3) {
        int j0 = role * 160;
        for (int idx = tid; idx < 76 * 160; idx += 352)
            sw4[idx] = g_dyn4[(idx / 160) * JPAD + j0 + (idx % 160)];
    } else {
        for (int idx = tid; idx < 38 * 32; idx += 352)
            sw4[idx] = g_dyn4[(38 + idx / 32) * JPAD + 480 + (idx % 32)];
    }
    if (tid < 4) vsm[150 + (tid >> 1) * 152 + (tid & 1)] = 0.f;  // pads 150,151,302,303
    __syncthreads();

    if (tid == 0) {
        mbar_init(base + OFF_GMB, 1);      mbar_init(base + OFF_GMB + 8, 1);
        mbar_init(base + OFF_TMB, 1);      mbar_init(base + OFF_TMB + 8, 1);
    }
    __syncthreads();
    if (tid == 0) {
        mbar_expect_tx(base + OFF_GMB,     GATE_TX);
        mbar_expect_tx(base + OFF_GMB + 8, GATE_TX);
        mbar_expect_tx(base + OFF_TMB,     4);
        mbar_expect_tx(base + OFF_TMB + 8, 4);
    }
    __syncthreads();

    uint32_t rb0 = mapa_rank(base, 0), rb1 = mapa_rank(base, 1);
    uint32_t rb2 = mapa_rank(base, 2), rb3 = mapa_rank(base, 3);

    float ba = 0.f, wa = 0.f;
    if (role == 3) { ba = *at_ba; wa = (tid < 20) ? at_Wa[tid] : 0.f; }

    cluster_sync2();                               // all barriers armed cluster-wide

    if (role == 0 && tid == 0) {                   // bootstrap ticket -> slot 0
        int e0 = atomicAdd(&g_ticket, 1);
        st_async_b32(rb0 + OFF_TICKBUF, (uint32_t)e0, rb0 + OFF_TMB);
        st_async_b32(rb1 + OFF_TICKBUF, (uint32_t)e0, rb1 + OFF_TMB);
        st_async_b32(rb2 + OFF_TICKBUF, (uint32_t)e0, rb2 + OFF_TMB);
        st_async_b32(rb3 + OFF_TICKBUF, (uint32_t)e0, rb3 + OFF_TMB);
    }

    int P = g_P;
    int epar = 0;
    uint32_t gph0 = 0, gph1 = 0;
    int tslot = 0; uint32_t tph0 = 0, tph1 = 0;

    while (true) {
        // ---- ticket rendezvous ----
        uint32_t tmbL = base + OFF_TMB + 8u * (uint32_t)tslot;
        mbar_wait(tmbL, tslot ? tph1 : tph0);
        if (tslot) tph1 ^= 1; else tph0 ^= 1;
        int r = tickbuf[tslot];
        __syncthreads();                           // all read before re-arm
        if (tid == 0) mbar_expect_tx(tmbL, 4);
        if (r >= P) break;
        bool sendNext = (role == 0 && tid == 0);
        tslot ^= 1;

        int t = __ldg(&g_path_top[r]);
        int v = t;
        while (true) {
            int d = __ldg(&g_desig[v]);
            if (__ldg(&g_run_of[d]) < 0) break;
            v = d;
        }
        int cache_id = -1;

        while (true) {                             // chain bottom-up
            int rid = __ldg(&g_run_of[v]);
            int es = __ldg(&g_run_start[rid]), ee = __ldg(&g_run_start[rid + 1]);

            float statv = 0.f;
            if (lowW)      statv = __ldg(&g_stat[(size_t)v * JPAD + role * 160 + tid]);
            else if (lowA) statv = __ldg(&g_stat[(size_t)v * JPAD + 480 + tid]);

            // prefetch first edge of run
            int ce = __ldg(&g_echild[es]);
            int c = ce & 0x7fffffff;
            bool cleaf = (ce < 0);
            float relv = 0.f, kprev = 0.f;
            if (lowW)      relv = __ldg(&g_rel[(size_t)c * JPAD + role * 160 + tid]);
            else if (lowA) relv = __ldg(&g_rel[(size_t)c * JPAD + 480 + tid]);
            if (cleaf) {
                if (lowW)      kprev = __ldg(&g_kpre[(size_t)c * JPAD + role * 160 + tid]);
                else if (lowA) kprev = __ldg(&g_kpre[(size_t)c * JPAD + 480 + tid]);
            }

            bool first = true;
            float hreg = 0.f;

            for (int e = es; e < ee; e++) {
                bool cached = (c == cache_id);
                float mx = 0.f, my = 0.f, mz = 0.f, mw = 0.f;

                // dedicated poller overlaps the h-matvec below
                if (tid == 320 && !cleaf && !cached) {
                    int n = 0;
                    while (!ld_acq(&g_child_ready[c])) { if (++n > 256) __nanosleep(32); }
                }
                if (!first && isw) {               // h-half, 19 rows per thread
                    const float4* wp = sw4 + col;
                    #pragma unroll
                    for (int r2 = 0; r2 < 19; r2++) {
                        float4 w = wp[(rh + r2) * 160]; float4 v4 = vsm4[rh + r2];
                        mx = fmaf(w.x, v4.x, mx); my = fmaf(w.y, v4.y, my);
                        mz = fmaf(w.z, v4.z, mz); mw = fmaf(w.w, v4.w, mw);
                    }
                }
                __syncthreads();                   // join poll + h-matvec

                if (!cleaf) {
                    if (!cached) {
                        if (tid < 150) vsm[152 + tid] = __ldcg(&g_state[c * MEM + tid]);
                        __syncthreads();
                    }
                    if (isw) {                     // k-half, 19 rows per thread
                        const float4* wp = sw4 + col;
                        #pragma unroll
                        for (int r2 = 0; r2 < 19; r2++) {
                            float4 w = wp[(38 + rh + r2) * 160]; float4 v4 = vsm4[38 + rh + r2];
                            mx = fmaf(w.x, v4.x, mx); my = fmaf(w.y, v4.y, my);
                            mz = fmaf(w.z, v4.z, mz); mw = fmaf(w.w, v4.w, mw);
                        }
                    } else if (isa) {              // attention k rows (role3 layout)
                        const float4* wp = sw4 + col;
                        #pragma unroll
                        for (int r2 = 0; r2 < 19; r2++) {
                            float4 w = wp[(rh + r2) * 32]; float4 v4 = vsm4[38 + rh + r2];
                            mx = fmaf(w.x, v4.x, mx); my = fmaf(w.y, v4.y, my);
                            mz = fmaf(w.z, v4.z, mz); mw = fmaf(w.w, v4.w, mw);
                        }
                    }
                }

                // upper halves publish partials
                float part = (mx + my) + (mz + mw);
                if ((role < 3 && tid >= 160 && tid < 320) || (role == 3 && tid >= 32 && tid < 64))
                    pbuf[col] = part;
                __syncthreads();

                // ---- lower halves finish + deliver via st.async ----
                uint32_t boff = (uint32_t)OFF_GMB + 8u * (uint32_t)epar;
                if (role < 3) {
                    if (tid < 150) {
                        float acc = statv + relv + kprev + part + pbuf[tid];
                        float gv = (role == 2) ? tanhf(acc) : sigf(acc);
                        uint32_t u = __float_as_uint(gv);
                        uint32_t doff = (uint32_t)OFF_GATE
                                      + (uint32_t)(epar * 480 + role * 160 + tid) * 4u;
                        st_async_b32(rb0 + doff, u, rb0 + boff);
                        st_async_b32(rb1 + doff, u, rb1 + boff);
                        st_async_b32(rb2 + doff, u, rb2 + boff);
                        st_async_b32(rb3 + doff, u, rb3 + boff);
                    }
                } else {
                    float av = 0.f;
                    if (tid < 20) {
                        float acc = statv + relv + kprev + part + pbuf[tid];
                        av = wa * tanhf(acc);
                    }
                    if (tid < 32) {
                        #pragma unroll
                        for (int o = 16; o; o >>= 1) av += __shfl_down_sync(0xffffffffu, av, o);
                        if (tid == 0) {
                            float a = sigf(av + ba);
                            uint32_t u = __float_as_uint(a);
                            uint32_t doff = (uint32_t)OFF_SA + 4u * (uint32_t)epar;
                            st_async_b32(rb0 + doff, u, rb0 + boff);
                            st_async_b32(rb1 + doff, u, rb1 + boff);
                            st_async_b32(rb2 + doff, u, rb2 + boff);
                            st_async_b32(rb3 + doff, u, rb3 + boff);
                        }
                    }
                }

                // ---- prefetch next edge (loads fly during the gate wait) ----
                int cnext = 0; bool cleafn = false;
                float relvn = 0.f, kprevn = 0.f;
                if (e + 1 < ee) {
                    int ce2 = __ldg(&g_echild[e + 1]);
                    cnext = ce2 & 0x7fffffff;
                    cleafn = (ce2 < 0);
                    if (lowW)      relvn = __ldg(&g_rel[(size_t)cnext * JPAD + role * 160 + tid]);
                    else if (lowA) relvn = __ldg(&g_rel[(size_t)cnext * JPAD + 480 + tid]);
                    if (cleafn) {
                        if (lowW)      kprevn = __ldg(&g_kpre[(size_t)cnext * JPAD + role * 160 + tid]);
                        else if (lowA) kprevn = __ldg(&g_kpre[(size_t)cnext * JPAD + 480 + tid]);
                    }
                }

                // ---- local rendezvous: wait own gate mbarrier ----
                uint32_t gmbL = base + boff;
                mbar_wait(gmbL, epar ? gph1 : gph0);
                if (epar) gph1 ^= 1; else gph0 ^= 1;

                // local combine (every CTA keeps its own h copy)
                float a = sa_sh[epar];
                if (tid < 150) {
                    const float* gb = gatebuf + epar * 480;
                    float z = gb[tid], r_ = gb[160 + tid], ht = gb[320 + tid];
                    float h = first ? 0.f : vsm[tid];
                    float m = r_ * h + (1.f - z) * ht;
                    hreg = a * m + (1.f - a) * h;
                    vsm[tid] = hreg;
                }
                __syncthreads();                   // gates consumed by all threads
                if (tid == 0) mbar_expect_tx(gmbL, GATE_TX);   // re-arm for edge+2
                if (sendNext) {
                    int rn = atomicAdd(&g_ticket, 1);
                    uint32_t tdoff = (uint32_t)OFF_TICKBUF + 4u * (uint32_t)tslot;
                    uint32_t tboff = (uint32_t)OFF_TMB + 8u * (uint32_t)tslot;
                    st_async_b32(rb0 + tdoff, (uint32_t)rn, rb0 + tboff);
                    st_async_b32(rb1 + tdoff, (uint32_t)rn, rb1 + tboff);
                    st_async_b32(rb2 + tdoff, (uint32_t)rn, rb2 + tboff);
                    st_async_b32(rb3 + tdoff, (uint32_t)rn, rb3 + tboff);
                    sendNext = false;
                }
                first = false;
                epar ^= 1;
                c = cnext; cleaf = cleafn; relv = relvn; kprev = kprevn;
            }

            if (v == t) {                          // chain top: publish + release
                if (role == 3) {
                    if (tid < 150) g_state[v * MEM + tid] = hreg;
                    __syncthreads();               // stores done block-wide
                    if (tid == 0) st_rel(&g_child_ready[v], 1);  // release orders them
                }
                break;
            }
            // chain transition: parent's first edge consumes K[v] from SMEM
            if (tid < 150) vsm[152 + tid] = hreg;
            __syncthreads();
            cache_id = v;
            v = __ldg(&g_parent_of[v]);
        }
    }
    cluster_sync2();
}

__global__ void k_out(float* __restrict__ out) {
    int m = threadIdx.x;
    if (m < MEM) out[m] = g_state[m];
}

// ---------------- launch ----------------
extern "C" void kernel_launch(void* const* d_in, const int* in_sizes, int n_in,
                              void* d_out, int out_size) {
    const float* w_emb   = (const float*)d_in[0];
    const float* tag_emb = (const float*)d_in[1];
    const float* rel_emb = (const float*)d_in[2];
    const float* leaf_h  = (const float*)d_in[3];
    const float* leaf_W  = (const float*)d_in[4];
    const float* leaf_U  = (const float*)d_in[5];
    const float* leaf_b  = (const float*)d_in[6];
    const float* node_W  = (const float*)d_in[7];
    const float* node_U  = (const float*)d_in[8];
    const float* node_b  = (const float*)d_in[9];
    const float* at_Wb   = (const float*)d_in[10];
    const float* at_bb   = (const float*)d_in[11];
    const float* at_Wa   = (const float*)d_in[12];
    const float* at_ba   = (const float*)d_in[13];
    const int*   edges   = (const int*)d_in[14];
    const int*   lids    = (const int*)d_in[15];

    int N = in_sizes[0] / 300;
    int E = in_sizes[14] / 2;
    int L = in_sizes[15];

    cudaFuncSetAttribute(k_edges, cudaFuncAttributeMaxDynamicSharedMemorySize, EDGE_SMEM);

    k_init<<<64, 256>>>(N, E);
    k_runscan<<<1, 1024>>>(edges, E);
    k_parent<<<(E + 255) / 256, 256>>>(edges, E);
    k_intlist<<<(N + 255) / 256, 256>>>(N);
    k_pathscan<<<1, 1024>>>(N);
    k_build_big<<<(320 * JPAD + 255) / 256, 256>>>(node_W, node_U, at_Wb, leaf_W);
    k_build_small<<<(21 * JPAD + 255) / 256, 256>>>(node_W, at_Wb, node_b, at_bb);
    k_c0<<<1, 512>>>(leaf_U, leaf_h, leaf_b);
    k_gemm<<<dim3((N + BM - 1) / BM, JPAD / BN), 256>>>(0, N, 320, w_emb, tag_emb, lids);
    k_gemm<<<dim3((L + BM - 1) / BM, JPAD / BN), 256>>>(1, L, 320, w_emb, tag_emb, lids);
    k_relpart<<<N, 512>>>(rel_emb);
    k_leafcomb<<<(L * MEM + 255) / 256, 256>>>(lids, leaf_h, L);
    k_gemm<<<dim3((L + BM - 1) / BM, JPAD / BN), 256>>>(2, L, 160, w_emb, tag_emb, lids);
    k_edges<<<4 * NCLUST, 352, EDGE_SMEM>>>(at_Wa, at_ba);
    k_out<<<1, 256>>>((float*)d_out);
}